// round 4
// baseline (speedup 1.0000x reference)
#include <cuda_runtime.h>

// out[b, j1*64 + j2] = x[b, 0, j1] * x[b, 1, j2]
// x: [32768, 2, 64] f32, out: [32768, 4096] f32
// 2 batch rows per CTA; 256 threads; each thread writes 8 floats per store via
// STG.256 (sm_100+ 256-bit stores), streaming (evict-first).

#define N_MF    64
#define ROW_IN  128   // 2 * 64 floats per batch row
#define ROW_OUT 4096
#define ROWS_PER_CTA 2

__device__ __forceinline__ void stg256_cs(float* addr,
                                          float v0, float v1, float v2, float v3,
                                          float v4, float v5, float v6, float v7) {
    asm volatile(
        "st.global.cs.v8.f32 [%0], {%1, %2, %3, %4, %5, %6, %7, %8};"
        :: "l"(addr),
           "f"(v0), "f"(v1), "f"(v2), "f"(v3),
           "f"(v4), "f"(v5), "f"(v6), "f"(v7)
        : "memory");
}

__global__ void __launch_bounds__(256, 8)
anfis_outer_kernel(const float* __restrict__ x, float* __restrict__ out) {
    const int b0  = blockIdx.x * ROWS_PER_CTA;
    const int tid = threadIdx.x;

    // [row][half][64]: half 0 = x[b,0,:], half 1 = x[b,1,:]
    __shared__ float s[ROWS_PER_CTA][2][N_MF];

    // Load 2*128 = 256 floats with 256 threads, one each (coalesced).
    {
        const int row = tid >> 7;           // 0..1
        const int off = tid & 127;          // 0..127
        ((float*)s[row])[off] = __ldg(x + (size_t)(b0 + row) * ROW_IN + off);
    }
    __syncthreads();

    const int tid8 = tid * 8;

    #pragma unroll
    for (int r = 0; r < ROWS_PER_CTA; ++r) {
        float* __restrict__ orow = out + (size_t)(b0 + r) * ROW_OUT;
        const float* __restrict__ sa = s[r][0];
        const float* __restrict__ sb = s[r][1];

        #pragma unroll
        for (int k = 0; k < 2; ++k) {
            const int idx = k * 2048 + tid8;      // multiple of 8
            const int j1  = idx >> 6;             // 0..63
            const int j2  = idx & 63;             // multiple of 8
            const float  av  = sa[j1];
            const float4 b0v = *reinterpret_cast<const float4*>(&sb[j2]);
            const float4 b1v = *reinterpret_cast<const float4*>(&sb[j2 + 4]);
            stg256_cs(orow + idx,
                      av * b0v.x, av * b0v.y, av * b0v.z, av * b0v.w,
                      av * b1v.x, av * b1v.y, av * b1v.z, av * b1v.w);
        }
    }
}

extern "C" void kernel_launch(void* const* d_in, const int* in_sizes, int n_in,
                              void* d_out, int out_size) {
    const float* x = (const float*)d_in[0];
    float* out = (float*)d_out;
    const int batch = in_sizes[0] / ROW_IN;              // 32768
    anfis_outer_kernel<<<batch / ROWS_PER_CTA, 256>>>(x, out);
}

// round 7
// speedup vs baseline: 1.0987x; 1.0987x over previous
#include <cuda_runtime.h>
#include <cstdint>

// out[b, j1*64 + j2] = x[b, 0, j1] * x[b, 1, j2]
// x: [32768, 2, 64] f32, out: [32768, 4096] f32
// 2 batch rows per CTA. Compute both rows into SMEM (32 KB), then one
// cp.async.bulk (TMA bulk store) delivers the contiguous 32 KB to GMEM
// with an L2 evict_first hint.

#define N_MF    64
#define ROW_IN  128    // 2 * 64 floats per batch row
#define ROW_OUT 4096
#define ROWS_PER_CTA 2
#define OUT_FLOATS (ROWS_PER_CTA * ROW_OUT)   // 8192 floats = 32 KB

__global__ void __launch_bounds__(256)
anfis_outer_tma_kernel(const float* __restrict__ x, float* __restrict__ out) {
    const int b0  = blockIdx.x * ROWS_PER_CTA;
    const int tid = threadIdx.x;

    __shared__ float sin[ROWS_PER_CTA][2][N_MF];
    __shared__ __align__(128) float sout[OUT_FLOATS];   // 32 KB staging

    // Load 2*128 = 256 input floats with 256 threads, one each (coalesced).
    {
        const int row = tid >> 7;           // 0..1
        const int off = tid & 127;          // 0..127
        ((float*)sin[row])[off] = __ldg(x + (size_t)(b0 + row) * ROW_IN + off);
    }
    __syncthreads();

    // Compute 8192 floats into SMEM: each thread 8x float4 STS (conflict-free).
    #pragma unroll
    for (int r = 0; r < ROWS_PER_CTA; ++r) {
        const float* __restrict__ sa = sin[r][0];
        const float* __restrict__ sb = sin[r][1];
        float4* __restrict__ so4 = reinterpret_cast<float4*>(&sout[r * ROW_OUT]);
        #pragma unroll
        for (int k = 0; k < 4; ++k) {
            const int idx = k * 1024 + tid * 4;   // multiple of 4
            const int j1  = idx >> 6;
            const int j2  = idx & 63;
            const float  av = sa[j1];
            const float4 bv = *reinterpret_cast<const float4*>(&sb[j2]);
            float4 v;
            v.x = av * bv.x;
            v.y = av * bv.y;
            v.z = av * bv.z;
            v.w = av * bv.w;
            so4[idx >> 2] = v;
        }
    }
    __syncthreads();

    // One thread issues a single 32 KB bulk store (async proxy).
    if (tid == 0) {
        uint32_t saddr;
        asm("{ .reg .u64 t; cvta.to.shared.u64 t, %1; cvt.u32.u64 %0, t; }"
            : "=r"(saddr) : "l"((const void*)sout));
        float* gptr = out + (size_t)b0 * ROW_OUT;

        asm volatile("fence.proxy.async.shared::cta;" ::: "memory");

        uint64_t pol;
        asm volatile("createpolicy.fractional.L2::evict_first.b64 %0, 1.0;"
                     : "=l"(pol));
        asm volatile(
            "cp.async.bulk.global.shared::cta.bulk_group.L2::cache_hint "
            "[%0], [%1], %2, %3;"
            :: "l"(gptr), "r"(saddr), "r"((uint32_t)(OUT_FLOATS * 4)), "l"(pol)
            : "memory");
        asm volatile("cp.async.bulk.commit_group;" ::: "memory");
        asm volatile("cp.async.bulk.wait_group 0;" ::: "memory");
    }
}

extern "C" void kernel_launch(void* const* d_in, const int* in_sizes, int n_in,
                              void* d_out, int out_size) {
    const float* x = (const float*)d_in[0];
    float* out = (float*)d_out;
    const int batch = in_sizes[0] / ROW_IN;              // 32768
    anfis_outer_tma_kernel<<<batch / ROWS_PER_CTA, 256>>>(x, out);
}